// round 15
// baseline (speedup 1.0000x reference)
#include <cuda_runtime.h>
#include <cuda_bf16.h>

// y = (x + 2) * 3 / 2 == fmaf(1.5f, x, 3.0f)
//
// FINAL: HBM-bound streaming kernel at the measured GB300 r+w ceiling
// (74.0-75.5us kernel, ~6.9 TB/s application traffic, ~81% of peak DRAM
// cycles). Config space exhaustively swept R1-R14 with
// predict->measure->post-mortem:
//   VPT {1,2,4,8,16}            -> in-flight bytes saturate; equal
//   128/256-bit vector ld/st    -> equal
//   block {256,512}             -> equal
//   tile {16,32,64} KB          -> equal
//   flat vs persistent grid     -> flat wins (HW work-steal > static bind)
//   load/store sw pipelining    -> equal
//   .cs vs .wt store policy     -> equal
//   occupancy 30-79%            -> non-binding
//   LSU path vs cp.async.bulk   -> bulk ~3% slower (mbarrier/drain cost;
//                                  DRAM ceiling is path-independent)
// Binding constraint: HBM3e bus turnaround + refresh — not software-
// addressable. Traffic is minimal (1 read + 1 write per element; an
// elementwise op has no reuse to exploit).
//
// Config: 512 threads x VPT=2 (16 KB/block, 16384 blocks, exact cover of
// 8192^2 — tail kernel never launches for this shape), 18 regs, 32-bit
// indexing, streaming cache hints.

constexpr int VPT = 2;                 // float4 per thread (32 B/thread)
constexpr int THREADS = 512;
constexpr int TILE = VPT * THREADS;    // float4 per block = 1024 (16 KB)

__global__ void __launch_bounds__(THREADS) fma_stream_kernel(
    const float4* __restrict__ in, float4* __restrict__ out)
{
    unsigned base = blockIdx.x * TILE + threadIdx.x;

    float4 v[VPT];
#pragma unroll
    for (int k = 0; k < VPT; k++)
        v[k] = __ldcs(in + base + k * THREADS);

#pragma unroll
    for (int k = 0; k < VPT; k++) {
        float4 r;
        r.x = fmaf(1.5f, v[k].x, 3.0f);
        r.y = fmaf(1.5f, v[k].y, 3.0f);
        r.z = fmaf(1.5f, v[k].z, 3.0f);
        r.w = fmaf(1.5f, v[k].w, 3.0f);
        __stcs(out + base + k * THREADS, r);
    }
}

// Generic remainder kernel (element granularity, any size).
__global__ void fma_tail_kernel(const float* __restrict__ in,
                                float* __restrict__ out,
                                long long start, long long n)
{
    long long i = start + (long long)blockIdx.x * blockDim.x + threadIdx.x;
    if (i < n) out[i] = fmaf(1.5f, in[i], 3.0f);
}

extern "C" void kernel_launch(void* const* d_in, const int* in_sizes, int n_in,
                              void* d_out, int out_size)
{
    const float* in = (const float*)d_in[0];
    float* out = (float*)d_out;
    long long n = (long long)in_sizes[0];

    long long n4 = n / 4;
    long long full_blocks = n4 / TILE;
    if (full_blocks > 0) {
        fma_stream_kernel<<<(unsigned)full_blocks, THREADS>>>(
            (const float4*)in, (float4*)out);
    }
    long long done = full_blocks * (long long)TILE * 4;  // elements handled
    long long tail = n - done;
    if (tail > 0) {
        fma_tail_kernel<<<(unsigned)((tail + 255) / 256), 256>>>(
            in, out, done, n);
    }
}

// round 16
// speedup vs baseline: 1.0203x; 1.0203x over previous
#include <cuda_runtime.h>
#include <cuda_bf16.h>

// y = (x + 2) * 3 / 2 == fmaf(1.5f, x, 3.0f)
//
// FINAL: HBM-bound streaming kernel at the measured GB300 r+w ceiling.
// Five repeat runs of this binary: kernel 74.4-75.6us, wall 81.2-82.0us,
// DRAM 80-82% of peak cycles (~6.9 TB/s application traffic) — that range
// is the platform noise distribution, not configuration signal.
//
// Config space exhaustively swept R1-R15 (predict -> measure -> post-mortem):
//   VPT {1,2,4,8,16}            -> in-flight bytes saturate; equal
//   128/256-bit vector ld/st    -> equal
//   block {256,512}             -> equal
//   tile {16,32,64} KB          -> equal
//   flat vs persistent grid     -> flat wins (HW work-steal > static bind)
//   load/store sw pipelining    -> equal
//   .cs vs .wt store policy     -> equal
//   occupancy 30-79%            -> non-binding
//   LSU path vs cp.async.bulk   -> bulk ~3% slower (mbarrier/drain cost;
//                                  DRAM ceiling is path-independent)
// Binding constraint: HBM3e bus turnaround + refresh — not software-
// addressable. Traffic is minimal: 1 read + 1 write per element, and an
// elementwise op has no reuse to exploit. This is the roofline.
//
// Config: 512 threads x VPT=2 (16 KB/block, 16384 blocks — exact cover of
// 8192^2, tail kernel never launches for this shape), 18 regs, 32-bit
// indexing, streaming cache hints.

constexpr int VPT = 2;                 // float4 per thread (32 B/thread)
constexpr int THREADS = 512;
constexpr int TILE = VPT * THREADS;    // float4 per block = 1024 (16 KB)

__global__ void __launch_bounds__(THREADS) fma_stream_kernel(
    const float4* __restrict__ in, float4* __restrict__ out)
{
    unsigned base = blockIdx.x * TILE + threadIdx.x;

    float4 v[VPT];
#pragma unroll
    for (int k = 0; k < VPT; k++)
        v[k] = __ldcs(in + base + k * THREADS);

#pragma unroll
    for (int k = 0; k < VPT; k++) {
        float4 r;
        r.x = fmaf(1.5f, v[k].x, 3.0f);
        r.y = fmaf(1.5f, v[k].y, 3.0f);
        r.z = fmaf(1.5f, v[k].z, 3.0f);
        r.w = fmaf(1.5f, v[k].w, 3.0f);
        __stcs(out + base + k * THREADS, r);
    }
}

// Generic remainder kernel (element granularity, any size).
__global__ void fma_tail_kernel(const float* __restrict__ in,
                                float* __restrict__ out,
                                long long start, long long n)
{
    long long i = start + (long long)blockIdx.x * blockDim.x + threadIdx.x;
    if (i < n) out[i] = fmaf(1.5f, in[i], 3.0f);
}

extern "C" void kernel_launch(void* const* d_in, const int* in_sizes, int n_in,
                              void* d_out, int out_size)
{
    const float* in = (const float*)d_in[0];
    float* out = (float*)d_out;
    long long n = (long long)in_sizes[0];

    long long n4 = n / 4;
    long long full_blocks = n4 / TILE;
    if (full_blocks > 0) {
        fma_stream_kernel<<<(unsigned)full_blocks, THREADS>>>(
            (const float4*)in, (float4*)out);
    }
    long long done = full_blocks * (long long)TILE * 4;  // elements handled
    long long tail = n - done;
    if (tail > 0) {
        fma_tail_kernel<<<(unsigned)((tail + 255) / 256), 256>>>(
            in, out, done, n);
    }
}